// round 6
// baseline (speedup 1.0000x reference)
#include <cuda_runtime.h>
#include <math.h>
#include <stdint.h>

// Problem constants (fixed by setup_inputs)
#define HH 512
#define WW 512
#define HW (HH * WW)            // 262144
#define VV 64
#define V3 (VV * VV * VV)       // 262144

// Reachability: d>0 && in-range forces cz = rint((d+2)*15.75) in [32,63].
// Per-batch scratch: [((cx*64+cy)*32 + (cz-32))] float4{count,r,g,b} = 2 MB.
#define SCR_PER_B (VV * VV * 32)    // 131072 entries

// Pipeline: 32 batches as NG groups of GB, double-buffered scratch.
#define GB 4
#define NG 8
#define GRP_SCR (GB * SCR_PER_B)    // 524288 entries = 8 MB per buffer
#define NBLK 148
#define NTHR 1024
#define NTH_ALL (NBLK * NTHR)       // 151552
#define QUADS_PER_GRP (GB * (HW / 4))   // 262144

__device__ __align__(128) float4 g_acc[2 * GRP_SCR];  // 16 MB, zero at load;
                                                      // finalize re-zeros.
__device__ unsigned g_splat_done[NG];                 // reset at kernel end
__device__ unsigned g_fin_done[NG];

// ---- policies / cache-op helpers -----------------------------------------
__device__ __forceinline__ uint64_t pol_evict_first() {
    uint64_t p;
    asm("createpolicy.fractional.L2::evict_first.b64 %0, 1.0;" : "=l"(p));
    return p;
}
__device__ __forceinline__ float4 ldg_stream(const float* a, uint64_t pol) {
    float4 v;
    asm("ld.global.nc.L2::cache_hint.v4.f32 {%0,%1,%2,%3}, [%4], %5;"
        : "=f"(v.x), "=f"(v.y), "=f"(v.z), "=f"(v.w) : "l"(a), "l"(pol));
    return v;
}
__device__ __forceinline__ void stg_stream(float* a, float4 v, uint64_t pol) {
    asm volatile("st.global.L2::cache_hint.v4.f32 [%0], {%1,%2,%3,%4}, %5;"
                 :: "l"(a), "f"(v.x), "f"(v.y), "f"(v.z), "f"(v.w), "l"(pol)
                 : "memory");
}
// Scratch access bypasses L1 (.cg): other SMs' REDs update L2 only.
__device__ __forceinline__ float4 ldcg4(const float4* a) {
    float4 v;
    asm volatile("ld.global.cg.v4.f32 {%0,%1,%2,%3}, [%4];"
                 : "=f"(v.x), "=f"(v.y), "=f"(v.z), "=f"(v.w) : "l"(a));
    return v;
}
__device__ __forceinline__ void stcg4(float4* a, float4 v) {
    asm volatile("st.global.cg.v4.f32 [%0], {%1,%2,%3,%4};"
                 :: "l"(a), "f"(v.x), "f"(v.y), "f"(v.z), "f"(v.w) : "memory");
}
__device__ __forceinline__ unsigned ld_acq(const unsigned* p) {
    unsigned v;
    asm volatile("ld.acquire.gpu.global.u32 %0, [%1];" : "=r"(v) : "l"(p)
                 : "memory");
    return v;
}
__device__ __forceinline__ void spin_until(const unsigned* ctr, unsigned tgt) {
    while (ld_acq(ctr) < tgt) __nanosleep(64);
}

// Branch-free resolve: count==0 => sums exactly 0 => sum*rcp(max(count,1))==0.
__device__ __forceinline__ void resolve(float4 a, float& occ, float& r,
                                        float& g, float& b) {
    float inv;
    asm("rcp.approx.f32 %0, %1;" : "=f"(inv) : "f"(fmaxf(a.x, 1.0f)));
    occ = (a.x > 0.0f) ? 1.0f : 0.0f;
    r = a.y * inv;
    g = a.z * inv;
    b = a.w * inv;
}

__global__ void __launch_bounds__(NTHR, 1)
fused_kernel(const float* __restrict__ rgbd, float* __restrict__ out) {
    const int bid = blockIdx.x;
    const int tid = threadIdx.x;
    const int gtid = bid * NTHR + tid;
    const uint64_t pfirst = pol_evict_first();

    for (int g = 0; g <= NG; g++) {
        // ---------------- splat group g into buf[g&1] ----------------
        if (g < NG) {
            if (g >= 2) {   // buffer reuse gate: finalize(g-2) must be done
                if (tid == 0) spin_until(&g_fin_done[g - 2], NBLK);
                __syncthreads();
            }
            float4* buf = &g_acc[(size_t)(g & 1) * GRP_SCR];

            for (int Q = gtid; Q < QUADS_PER_GRP; Q += NTH_ALL) {
                int bl = Q >> 16;            // batch within group
                int p = (Q & 65535) << 2;    // pixel index (mult of 4)
                int h = p >> 9;
                int w0 = p & (WW - 1);
                const float* base =
                    rgbd + (size_t)(g * GB + bl) * (4 * HW);

                float4 d4 = ldg_stream(base + 3 * HW + p, pfirst);
                float dv[4] = {d4.x, d4.y, d4.z, d4.w};
                int   lin[4];
                bool  valid[4];
                bool  any = false;
                float yb = (float)h - 256.0f;   // fx=fy=256, cx=cy=256

                #pragma unroll
                for (int k = 0; k < 4; k++) {
                    float d = dv[k];
                    bool ok = (d > 0.0f) && (d < 10.0f) && isfinite(d);
                    float x = ((float)(w0 + k) - 256.0f) * d * (1.0f / 256.0f);
                    float y = yb * d * (1.0f / 256.0f);
                    // rintf = round-half-even = jnp.round; 15.75 == 63/4
                    // exactly -> same single rounding as the reference.
                    float fx_ = rintf((x + 2.0f) * 15.75f);
                    float fy_ = rintf((y + 2.0f) * 15.75f);
                    float fz_ = rintf((d + 2.0f) * 15.75f);
                    ok = ok && (fx_ >= 0.0f) && (fx_ <= 63.0f)
                            && (fy_ >= 0.0f) && (fy_ <= 63.0f)
                            && (fz_ >= 32.0f) && (fz_ <= 63.0f);
                    valid[k] = ok;
                    any = any || ok;
                    int cx = (int)fx_, cy = (int)fy_, cz = (int)fz_;
                    lin[k] = bl * SCR_PER_B +
                             (((((cx << 6) | cy) << 5)) | (cz - 32));
                }

                if (!any) continue;

                float4 r4 = ldg_stream(base + 0 * HW + p, pfirst);
                float4 g4 = ldg_stream(base + 1 * HW + p, pfirst);
                float4 b4 = ldg_stream(base + 2 * HW + p, pfirst);
                float rv[4] = {r4.x, r4.y, r4.z, r4.w};
                float gv[4] = {g4.x, g4.y, g4.z, g4.w};
                float bv[4] = {b4.x, b4.y, b4.z, b4.w};

                #pragma unroll
                for (int k = 0; k < 4; k++) {
                    if (valid[k]) {
                        float* a = (float*)&buf[lin[k]];
                        asm volatile(
                            "red.global.add.v4.f32 [%0], {%1,%2,%3,%4};"
                            :: "l"(a), "f"(1.0f), "f"(rv[k]), "f"(gv[k]),
                               "f"(bv[k]) : "memory");
                    }
                }
            }
            __threadfence();
            __syncthreads();
            if (tid == 0) atomicAdd(&g_splat_done[g], 1u);
        }

        // -------------- finalize group g-1 from buf[(g-1)&1] --------------
        if (g >= 1) {
            int fg = g - 1;
            if (tid == 0) spin_until(&g_splat_done[fg], NBLK);
            __syncthreads();
            float4* buf = &g_acc[(size_t)(fg & 1) * GRP_SCR];
            float4 z = make_float4(0.f, 0.f, 0.f, 0.f);

            for (int S = gtid; S < GRP_SCR / 4; S += NTH_ALL) {
                int s = S << 2;                   // 4 contiguous entries
                int bl = s >> 17;                 // batch within group
                int sl = s & (SCR_PER_B - 1);     // ((cx*64+cy)*32 + cz-32)

                float4 a0 = ldcg4(&buf[s + 0]);
                float4 a1 = ldcg4(&buf[s + 1]);
                float4 a2 = ldcg4(&buf[s + 2]);
                float4 a3 = ldcg4(&buf[s + 3]);
                // rezero for reuse two groups later (stays dirty in L2)
                stcg4(&buf[s + 0], z); stcg4(&buf[s + 1], z);
                stcg4(&buf[s + 2], z); stcg4(&buf[s + 3], z);

                float4 occ, rr, gg, bb;
                resolve(a0, occ.x, rr.x, gg.x, bb.x);
                resolve(a1, occ.y, rr.y, gg.y, bb.y);
                resolve(a2, occ.z, rr.z, gg.z, bb.z);
                resolve(a3, occ.w, rr.w, gg.w, bb.w);

                int rhi = (sl >> 5) << 6;         // (cx*64+cy)*64
                int rocc = rhi + (sl & 31) + 32;  // occupied half
                int rzer = rhi + (sl & 31);       // zero half
                float* ob = out + (size_t)(fg * GB + bl) * (4 * V3);

                stg_stream(ob + rocc,          occ, pfirst);
                stg_stream(ob + V3 + rocc,     rr,  pfirst);
                stg_stream(ob + 2 * V3 + rocc, gg,  pfirst);
                stg_stream(ob + 3 * V3 + rocc, bb,  pfirst);
                stg_stream(ob + rzer,          z, pfirst);
                stg_stream(ob + V3 + rzer,     z, pfirst);
                stg_stream(ob + 2 * V3 + rzer, z, pfirst);
                stg_stream(ob + 3 * V3 + rzer, z, pfirst);
            }
            __threadfence();
            __syncthreads();
            if (tid == 0) atomicAdd(&g_fin_done[fg], 1u);
        }
    }

    // -------- reset counters for next graph replay (block 0 only) --------
    if (bid == 0) {
        if (tid == 0) spin_until(&g_fin_done[NG - 1], NBLK);
        __syncthreads();
        if (tid < NG) {
            g_splat_done[tid] = 0;
            g_fin_done[tid] = 0;
        }
        __threadfence();
    }
}

extern "C" void kernel_launch(void* const* d_in, const int* in_sizes, int n_in,
                              void* d_out, int out_size) {
    const float* rgbd = (const float*)d_in[0];
    float* out = (float*)d_out;
    fused_kernel<<<NBLK, NTHR>>>(rgbd, out);
}